// round 15
// baseline (speedup 1.0000x reference)
#include <cuda_runtime.h>
#include <cuda_bf16.h>
#include <cuda_fp16.h>
#include <cstdint>
#include <cstddef>

#define B_DIM 32
#define HDIM  512
#define NDIM  4096
#define MDIM  128
#define TDIM  256

// __device__ scratch. WpT bf16 hi/lo (GEMM1, 3-split); Wp single fp16 (GEMM2).
__device__ __align__(16) __nv_bfloat16 g_WpT_hi[B_DIM * MDIM * HDIM]; // [b][m][h]
__device__ __align__(16) __nv_bfloat16 g_WpT_lo[B_DIM * MDIM * HDIM];
__device__ __align__(16) __half        g_Wp_f16[B_DIM * HDIM * MDIM]; // [b][h][m]

// ---------------- helpers (all non-arch-specific PTX) ----------------
__device__ __forceinline__ uint32_t smem_u32(const void* p) {
    uint32_t a;
    asm("{ .reg .u64 t; cvta.to.shared.u64 t, %1; cvt.u32.u64 %0, t; }"
        : "=r"(a) : "l"(p));
    return a;
}
__device__ __forceinline__ void ldsm4(uint32_t* r, uint32_t a) {
    asm volatile("ldmatrix.sync.aligned.m8n8.x4.shared.b16 {%0,%1,%2,%3}, [%4];"
        : "=r"(r[0]), "=r"(r[1]), "=r"(r[2]), "=r"(r[3]) : "r"(a));
}
__device__ __forceinline__ void ldsm4t(uint32_t* r, uint32_t a) {
    asm volatile("ldmatrix.sync.aligned.m8n8.x4.trans.shared.b16 {%0,%1,%2,%3}, [%4];"
        : "=r"(r[0]), "=r"(r[1]), "=r"(r[2]), "=r"(r[3]) : "r"(a));
}
__device__ __forceinline__ void mma16816(float* d, const uint32_t* a,
                                         uint32_t b0, uint32_t b1) {
    asm volatile(
        "mma.sync.aligned.m16n8k16.row.col.f32.bf16.bf16.f32 "
        "{%0,%1,%2,%3}, {%4,%5,%6,%7}, {%8,%9}, {%0,%1,%2,%3};"
        : "+f"(d[0]), "+f"(d[1]), "+f"(d[2]), "+f"(d[3])
        : "r"(a[0]), "r"(a[1]), "r"(a[2]), "r"(a[3]), "r"(b0), "r"(b1));
}
__device__ __forceinline__ void mma16816f(float* d, const uint32_t* a,
                                          uint32_t b0, uint32_t b1) {
    asm volatile(
        "mma.sync.aligned.m16n8k16.row.col.f32.f16.f16.f32 "
        "{%0,%1,%2,%3}, {%4,%5,%6,%7}, {%8,%9}, {%0,%1,%2,%3};"
        : "+f"(d[0]), "+f"(d[1]), "+f"(d[2]), "+f"(d[3])
        : "r"(a[0]), "r"(a[1]), "r"(a[2]), "r"(a[3]), "r"(b0), "r"(b1));
}
__device__ __forceinline__ void split2(float x, float y, uint32_t& hi, uint32_t& lo) {
    __nv_bfloat16 xh = __float2bfloat16(x);
    __nv_bfloat16 yh = __float2bfloat16(y);
    __nv_bfloat16 xl = __float2bfloat16(x - __bfloat162float(xh));
    __nv_bfloat16 yl = __float2bfloat16(y - __bfloat162float(yh));
    hi = (uint32_t)__bfloat16_as_ushort(xh) | ((uint32_t)__bfloat16_as_ushort(yh) << 16);
    lo = (uint32_t)__bfloat16_as_ushort(xl) | ((uint32_t)__bfloat16_as_ushort(yl) << 16);
}
__device__ __forceinline__ uint32_t packh2(float x, float y) {
    __half2 h = __floats2half2_rn(x, y);
    return *(uint32_t*)&h;
}
#define CP_ASYNC16(dst, src)                                                   \
    asm volatile("cp.async.cg.shared.global [%0], [%1], 16;"                   \
                 :: "r"(dst), "l"(src))
#define CP_COMMIT() asm volatile("cp.async.commit_group;" ::: "memory")
#define CP_WAIT(n)  asm volatile("cp.async.wait_group %0;" :: "n"(n) : "memory")

// ============================================================
// Kernel 1 (unchanged): WpT bf16 hi/lo + Wp fp16 via 3-split MMA.
// ============================================================
#define PPADA 136
#define PPADB 40
#define PSTG  133
#define POFF_A  0
#define PA_HALF 8704
#define POFF_B  17408
#define PB_HALF 10240
#define PSMEM   69632

__global__ __launch_bounds__(256) void proj_kernel(const float* __restrict__ W,
                                                   const float* __restrict__ head_w) {
    extern __shared__ char smem[];
    const uint32_t sbase = smem_u32(smem);

    const int tid = threadIdx.x;
    const int wid = tid >> 5;
    const int lid = tid & 31;
    const int b   = blockIdx.y;
    const int h0  = blockIdx.x * 128;

    const float* Wb = W + (size_t)b * TDIM * MDIM;

    const int g  = lid >> 3, lr = lid & 7;
    const int arow = ((g & 2) ? 8 : 0) + lr;
    const int acol = wid * 16 + ((g & 1) ? 8 : 0);
    const uint32_t a_off = (uint32_t)(arow * PPADA + acol) * 2;
    const int brow = ((g >> 1) ? 8 : 0) + lr;
    const int bcol = (g & 1) ? 8 : 0;
    const uint32_t b_off = (uint32_t)(brow * PPADB + bcol) * 2;

    float4 ra[4], rb[4];
    auto ldg_chunk = [&](int kc) {
#pragma unroll
        for (int it = 0; it < 4; it++) {
            int fa = it * 256 + tid;
            int ar = fa >> 5, ac4 = (fa & 31) << 2;
            ra[it] = *(const float4*)(Wb + (size_t)(kc * 32 + ar) * MDIM + ac4);
            int br = fa >> 3, bc4 = (fa & 7) << 2;
            rb[it] = *(const float4*)(head_w + (size_t)(h0 + br) * TDIM + kc * 32 + bc4);
        }
    };
    auto conv_chunk = [&]() {
#pragma unroll
        for (int it = 0; it < 4; it++) {
            int fa = it * 256 + tid;
            int ar = fa >> 5, ac4 = (fa & 31) << 2;
            uint32_t h01, l01, h23, l23;
            split2(ra[it].x, ra[it].y, h01, l01);
            split2(ra[it].z, ra[it].w, h23, l23);
            uint32_t off = (uint32_t)(ar * PPADA + ac4) * 2;
            *(uint2*)(smem + POFF_A + off)            = make_uint2(h01, h23);
            *(uint2*)(smem + POFF_A + PA_HALF + off)  = make_uint2(l01, l23);
            int br = fa >> 3, bc4 = (fa & 7) << 2;
            split2(rb[it].x, rb[it].y, h01, l01);
            split2(rb[it].z, rb[it].w, h23, l23);
            off = (uint32_t)(br * PPADB + bc4) * 2;
            *(uint2*)(smem + POFF_B + off)            = make_uint2(h01, h23);
            *(uint2*)(smem + POFF_B + PB_HALF + off)  = make_uint2(l01, l23);
        }
    };

    float sacc[16][4];
#pragma unroll
    for (int t = 0; t < 16; t++)
#pragma unroll
        for (int j = 0; j < 4; j++) sacc[t][j] = 0.f;

    ldg_chunk(0);
    for (int kc = 0; kc < 8; kc++) {
        conv_chunk();
        __syncthreads();
        if (kc < 7) ldg_chunk(kc + 1);

        const uint32_t ahi = sbase + POFF_A, alo = ahi + PA_HALF;
        const uint32_t bhi = sbase + POFF_B, blo = bhi + PB_HALF;
#pragma unroll
        for (int kk = 0; kk < 2; kk++) {
            uint32_t ah[4], al[4];
            uint32_t aoff = a_off + (uint32_t)(kk * 16 * PPADA) * 2;
            ldsm4t(ah, ahi + aoff);
            ldsm4t(al, alo + aoff);
#pragma unroll
            for (int pr = 0; pr < 4; pr++) {
                uint32_t bh0[4], bl0[4], bh1[4], bl1[4];
                uint32_t bo0 = b_off + (uint32_t)((2 * pr) * 16 * PPADB + kk * 16) * 2;
                uint32_t bo1 = b_off + (uint32_t)((2 * pr + 1) * 16 * PPADB + kk * 16) * 2;
                ldsm4(bh0, bhi + bo0);
                ldsm4(bh1, bhi + bo1);
                ldsm4(bl0, blo + bo0);
                ldsm4(bl1, blo + bo1);
                float* A0 = sacc[4 * pr + 0];
                float* A1 = sacc[4 * pr + 1];
                float* A2 = sacc[4 * pr + 2];
                float* A3 = sacc[4 * pr + 3];
                mma16816(A0, ah, bh0[0], bh0[1]);
                mma16816(A1, ah, bh0[2], bh0[3]);
                mma16816(A2, ah, bh1[0], bh1[1]);
                mma16816(A3, ah, bh1[2], bh1[3]);
                mma16816(A0, ah, bl0[0], bl0[1]);
                mma16816(A1, ah, bl0[2], bl0[3]);
                mma16816(A2, ah, bl1[0], bl1[1]);
                mma16816(A3, ah, bl1[2], bl1[3]);
                mma16816(A0, al, bh0[0], bh0[1]);
                mma16816(A1, al, bh0[2], bh0[3]);
                mma16816(A2, al, bh1[0], bh1[1]);
                mma16816(A3, al, bh1[2], bh1[3]);
            }
        }
        __syncthreads();
    }

    float* stg = (float*)smem;
    const int rr = lid >> 2, qq = lid & 3;
#pragma unroll
    for (int t = 0; t < 16; t++) {
        int hcl = t * 8 + 2 * qq;
        int m   = wid * 16 + rr;
        stg[(size_t)m * PSTG + hcl]           = sacc[t][0];
        stg[(size_t)m * PSTG + hcl + 1]       = sacc[t][1];
        stg[(size_t)(m + 8) * PSTG + hcl]     = sacc[t][2];
        stg[(size_t)(m + 8) * PSTG + hcl + 1] = sacc[t][3];
    }
    __syncthreads();

#pragma unroll
    for (int it = 0; it < 16; it++) {
        int f = it * 256 + tid;
        int m = f >> 5, c4 = (f & 31) << 2;
        const float* s = stg + (size_t)m * PSTG + c4;
        uint32_t h01, l01, h23, l23;
        split2(s[0], s[1], h01, l01);
        split2(s[2], s[3], h23, l23);
        size_t base = ((size_t)b * MDIM + m) * HDIM + h0 + c4;
        *(uint2*)(g_WpT_hi + base) = make_uint2(h01, h23);
        *(uint2*)(g_WpT_lo + base) = make_uint2(l01, l23);
    }
#pragma unroll
    for (int it = 0; it < 16; it++) {
        int f = it * 256 + tid;
        int h = f >> 5, m4 = (f & 31) << 2;
        float x0 = stg[(size_t)(m4 + 0) * PSTG + h];
        float x1 = stg[(size_t)(m4 + 1) * PSTG + h];
        float x2 = stg[(size_t)(m4 + 2) * PSTG + h];
        float x3 = stg[(size_t)(m4 + 3) * PSTG + h];
        uint32_t p01 = packh2(x0, x1), p23 = packh2(x2, x3);
        size_t base = ((size_t)b * HDIM + h0 + h) * MDIM + m4;
        *(uint2*)(g_Wp_f16 + base) = make_uint2(p01, p23);
    }
}

// ============================================================
// Kernel 2: GEMM1 m-split (as R14). GEMM2 NOW 2x2 warp split:
// warp w owns n32 = (w&1)*32, h32 = (w>>1)*32 -> W-tile LDSM
// redundancy 4x -> 2x (E fragments resident: 64 regs, loaded once).
// Bit-identical accumulation order -> same rel_err as R14.
// 4 CTAs/SM.
// ============================================================
#define PADQ 72
#define PADK 40
#define PADW 136
#define PADE 136
#define STGS 68
#define OFF_KB  0
#define KB_SZ   20480
#define OFF_Q   40960
#define OFF_WB  0
#define WB_SZ   17408
#define OFF_E   34816
#define OFF_STG 34816
#define OFF_RCP 52224
#define SMEM_DYN 52480

__global__ __launch_bounds__(128, 4)
void attn_kernel(const float* __restrict__ H, float* __restrict__ out) {
    extern __shared__ char smem[];
    const uint32_t sbase = smem_u32(smem);

    const int tid = threadIdx.x;
    const int wid = tid >> 5;
    const int lid = tid & 31;
    const int b   = blockIdx.y;
    const int n0  = blockIdx.x * 64;

    const float* Hb = H + (size_t)b * HDIM * NDIM + n0;
    const __nv_bfloat16* KTh = g_WpT_hi + (size_t)b * MDIM * HDIM;
    const __nv_bfloat16* KTl = g_WpT_lo + (size_t)b * MDIM * HDIM;
    const __half*        Wpf = g_Wp_f16 + (size_t)b * HDIM * MDIM;

    const int g  = lid >> 3, lr = lid & 7;
    const int rr = lid >> 2, qq = lid & 3;
    // GEMM1 A (trans ldsm): rows k, cols n
    const int arow_k = ((g & 2) ? 8 : 0) + lr;
    const int acq    = (g & 1) ? 8 : 0;
    // B (non-trans ldsm): rows = tile rows, col halves by k
    const int brow_m = ((g >> 1) ? 8 : 0) + lr;
    const int bcq    = (g & 1) ? 8 : 0;
    // GEMM2 A (E, non-trans ldsm from [n][k])
    const int earow = ((g & 1) ? 8 : 0) + lr;
    // GEMM2 2x2 warp split
    const int nb = (wid & 1) * 32;
    const int hb = (wid >> 1) * 32;

    auto issue_k = [&](int hc, int p) {
        uint32_t dh = sbase + OFF_KB + p * KB_SZ;
        uint32_t dl = dh + 10240;
        int k0 = hc * 32;
#pragma unroll
        for (int it = 0; it < 4; it++) {
            int f = it * 128 + tid, m = f >> 2, c8 = (f & 3) << 3;
            uint32_t o = (uint32_t)(m * PADK + c8) * 2;
            CP_ASYNC16(dh + o, KTh + (size_t)m * HDIM + k0 + c8);
            CP_ASYNC16(dl + o, KTl + (size_t)m * HDIM + k0 + c8);
        }
    };
    auto issue_w = [&](int hc2, int p) {
        uint32_t dw = sbase + OFF_WB + p * WB_SZ;
#pragma unroll
        for (int it = 0; it < 8; it++) {
            int f = it * 128 + tid, hr = f >> 4, c8 = (f & 15) << 3;
            uint32_t o = (uint32_t)(hr * PADW + c8) * 2;
            CP_ASYNC16(dw + o, Wpf + (size_t)(hc2 * 64 + hr) * MDIM + c8);
        }
    };
    auto ldg_q = [&](int hc, float4* qv) {
#pragma unroll
        for (int it = 0; it < 4; it++) {
            int f = it * 128 + tid, hr = f >> 4, c4 = (f & 15) << 2;
            qv[it] = *(const float4*)(Hb + (size_t)(hc * 32 + hr) * NDIM + c4);
        }
    };
    auto conv_q = [&](const float4* qv) {
#pragma unroll
        for (int it = 0; it < 4; it++) {
            int f = it * 128 + tid, hr = f >> 4, c4 = (f & 15) << 2;
            uint32_t h01, l01, h23, l23;
            split2(qv[it].x, qv[it].y, h01, l01);
            split2(qv[it].z, qv[it].w, h23, l23);
            uint32_t off = (uint32_t)(hr * PADQ + c4) * 2;
            *(uint2*)(smem + OFF_Q + off)        = make_uint2(h01, h23);
            *(uint2*)(smem + OFF_Q + 4608 + off) = make_uint2(l01, l23);
        }
    };

    // ------ GEMM1 (m-split, unchanged from R14) ------
    float sacc[16][4];
#pragma unroll
    for (int t = 0; t < 16; t++)
#pragma unroll
        for (int j = 0; j < 4; j++) sacc[t][j] = 0.f;

    float4 qv[4];
    issue_k(0, 0); CP_COMMIT();
    ldg_q(0, qv);
    conv_q(qv);
    ldg_q(1, qv);

    const uint32_t qhi = sbase + OFF_Q;
    const uint32_t qlo = qhi + 4608;

    for (int hc = 0; hc < 16; hc++) {
        const int p = hc & 1;
        CP_WAIT(0);
        __syncthreads();
        if (hc < 15) { issue_k(hc + 1, p ^ 1); CP_COMMIT(); }

        const uint32_t khi = sbase + OFF_KB + p * KB_SZ;
        const uint32_t klo = khi + 10240;
#pragma unroll
        for (int kk = 0; kk < 2; kk++) {
            uint32_t bh0[4], bl0[4], bh1[4], bl1[4];
            uint32_t bo0 = (uint32_t)((32 * wid + brow_m) * PADK + bcq + kk * 16) * 2;
            uint32_t bo1 = bo0 + (uint32_t)(16 * PADK) * 2;
            ldsm4(bh0, khi + bo0);
            ldsm4(bh1, khi + bo1);
            ldsm4(bl0, klo + bo0);
            ldsm4(bl1, klo + bo1);
#pragma unroll
            for (int nt = 0; nt < 4; nt++) {
                uint32_t ah[4], al[4];
                uint32_t ao = (uint32_t)((arow_k + kk * 16) * PADQ + nt * 16 + acq) * 2;
                ldsm4t(ah, qhi + ao);
                ldsm4t(al, qlo + ao);
                float* A0 = sacc[nt * 4 + 0];
                float* A1 = sacc[nt * 4 + 1];
                float* A2 = sacc[nt * 4 + 2];
                float* A3 = sacc[nt * 4 + 3];
                mma16816(A0, ah, bh0[0], bh0[1]);
                mma16816(A1, ah, bh0[2], bh0[3]);
                mma16816(A2, ah, bh1[0], bh1[1]);
                mma16816(A3, ah, bh1[2], bh1[3]);
                mma16816(A0, ah, bl0[0], bl0[1]);
                mma16816(A1, ah, bl0[2], bl0[3]);
                mma16816(A2, ah, bl1[0], bl1[1]);
                mma16816(A3, ah, bl1[2], bl1[3]);
                mma16816(A0, al, bh0[0], bh0[1]);
                mma16816(A1, al, bh0[2], bh0[3]);
                mma16816(A2, al, bh1[0], bh1[1]);
                mma16816(A3, al, bh1[2], bh1[3]);
            }
        }
        __syncthreads();
        if (hc < 15) conv_q(qv);
        if (hc < 14) ldg_q(hc + 2, qv);
    }

    // prefetch GEMM2 chunk 0 (WB0 aliases dead KB0)
    issue_w(0, 0); CP_COMMIT();

    // ---------------- softmax over m (cross-warp m-reduction) ----------------
    float* pm = (float*)(smem + OFF_E);          // [4 warps][64 n]
    float* ps = (float*)(smem + OFF_E + 1024);   // [4 warps][64 n]
    float* rcp = (float*)(smem + OFF_RCP);       // [64 n]

    float mx[4][2];
#pragma unroll
    for (int nt = 0; nt < 4; nt++) { mx[nt][0] = -3.4e38f; mx[nt][1] = -3.4e38f; }
#pragma unroll
    for (int t = 0; t < 16; t++) {
        int nt = t >> 2;
        mx[nt][0] = fmaxf(mx[nt][0], fmaxf(sacc[t][0], sacc[t][1]));
        mx[nt][1] = fmaxf(mx[nt][1], fmaxf(sacc[t][2], sacc[t][3]));
    }
#pragma unroll
    for (int nt = 0; nt < 4; nt++)
#pragma unroll
        for (int hf = 0; hf < 2; hf++) {
            mx[nt][hf] = fmaxf(mx[nt][hf], __shfl_xor_sync(0xFFFFFFFFu, mx[nt][hf], 1));
            mx[nt][hf] = fmaxf(mx[nt][hf], __shfl_xor_sync(0xFFFFFFFFu, mx[nt][hf], 2));
        }
    if (qq == 0) {
#pragma unroll
        for (int nt = 0; nt < 4; nt++)
#pragma unroll
            for (int hf = 0; hf < 2; hf++)
                pm[wid * 64 + nt * 16 + hf * 8 + rr] = mx[nt][hf];
    }
    __syncthreads();
    float rmax[4][2];
#pragma unroll
    for (int nt = 0; nt < 4; nt++)
#pragma unroll
        for (int hf = 0; hf < 2; hf++) {
            int n = nt * 16 + hf * 8 + rr;
            float v = fmaxf(pm[n], pm[64 + n]);
            v = fmaxf(v, fmaxf(pm[128 + n], pm[192 + n]));
            rmax[nt][hf] = v;
        }
    float sm[4][2];
#pragma unroll
    for (int nt = 0; nt < 4; nt++) { sm[nt][0] = 0.f; sm[nt][1] = 0.f; }
#pragma unroll
    for (int t = 0; t < 16; t++) {
        int nt = t >> 2;
        sacc[t][0] = __expf(sacc[t][0] - rmax[nt][0]);
        sacc[t][1] = __expf(sacc[t][1] - rmax[nt][0]);
        sacc[t][2] = __expf(sacc[t][2] - rmax[nt][1]);
        sacc[t][3] = __expf(sacc[t][3] - rmax[nt][1]);
        sm[nt][0] += sacc[t][0] + sacc[t][1];
        sm[nt][1] += sacc[t][2] + sacc[t][3];
    }
#pragma unroll
    for (int nt = 0; nt < 4; nt++)
#pragma unroll
        for (int hf = 0; hf < 2; hf++) {
            sm[nt][hf] += __shfl_xor_sync(0xFFFFFFFFu, sm[nt][hf], 1);
            sm[nt][hf] += __shfl_xor_sync(0xFFFFFFFFu, sm[nt][hf], 2);
        }
    if (qq == 0) {
#pragma unroll
        for (int nt = 0; nt < 4; nt++)
#pragma unroll
            for (int hf = 0; hf < 2; hf++)
                ps[wid * 64 + nt * 16 + hf * 8 + rr] = sm[nt][hf];
    }
    __syncthreads();
    if (wid == 0 && qq == 0) {
#pragma unroll
        for (int nt = 0; nt < 4; nt++)
#pragma unroll
            for (int hf = 0; hf < 2; hf++) {
                int n = nt * 16 + hf * 8 + rr;
                rcp[n] = 1.0f / (ps[n] + ps[64 + n] + ps[128 + n] + ps[192 + n]);
            }
    }
    __syncthreads();   // all ps/pm reads done; E may overwrite the area

    // ---- write unnormalized E (fp16) to smem [n64][m128], stride PADE ----
#pragma unroll
    for (int t = 0; t < 16; t++) {
        int nt = t >> 2, u = t & 3;
        int m  = 32 * wid + (u >> 1) * 16 + (u & 1) * 8 + 2 * qq;
        int nr = nt * 16 + rr;
        *(uint32_t*)(smem + OFF_E + (size_t)nr * (PADE * 2) + m * 2) =
            packh2(sacc[t][0], sacc[t][1]);
        *(uint32_t*)(smem + OFF_E + (size_t)(nr + 8) * (PADE * 2) + m * 2) =
            packh2(sacc[t][2], sacc[t][3]);
    }
    __syncthreads();

    // ---- reload E as GEMM2 A-fragments: warp owns n32 slice (nb) ----
    uint32_t ef[8][2][4];
#pragma unroll
    for (int kk = 0; kk < 8; kk++)
#pragma unroll
        for (int nt = 0; nt < 2; nt++)
            ldsm4(ef[kk][nt],
                  sbase + OFF_E +
                  (uint32_t)((nb + nt * 16 + earow) * PADE +
                             ((g & 2) ? 8 : 0) + kk * 16) * 2);
    float rc[2][2];
#pragma unroll
    for (int nt = 0; nt < 2; nt++) {
        rc[nt][0] = ((float*)(smem + OFF_RCP))[nb + nt * 16 + rr];
        rc[nt][1] = ((float*)(smem + OFF_RCP))[nb + nt * 16 + rr + 8];
    }

    // -------- GEMM2 (2x2 split): C[n][h] = sum_m E[n][m] * Wp[h][m] --------
    float* outb = out + (size_t)b * HDIM * NDIM;
    float* stg = (float*)(smem + OFF_STG);

    for (int hc2 = 0; hc2 < 8; hc2++) {
        const int p = hc2 & 1;
        CP_WAIT(0);
        __syncthreads();                 // WB[p] visible; STG free (ef loaded)
        if (hc2 < 7) { issue_w(hc2 + 1, p ^ 1); CP_COMMIT(); }

        float cacc[8][4];
#pragma unroll
        for (int t = 0; t < 8; t++)
#pragma unroll
            for (int j = 0; j < 4; j++) cacc[t][j] = 0.f;

        const uint32_t wb = sbase + OFF_WB + p * WB_SZ;
#pragma unroll
        for (int kk = 0; kk < 8; kk++) {
            uint32_t w0[4], w1[4];
            uint32_t wo = (uint32_t)((hb + brow_m) * PADW + bcq + kk * 16) * 2;
            ldsm4(w0, wb + wo);
            ldsm4(w1, wb + wo + (uint32_t)(16 * PADW) * 2);
#pragma unroll
            for (int nt = 0; nt < 2; nt++) {
                mma16816f(cacc[nt * 4 + 0], ef[kk][nt], w0[0], w0[1]);
                mma16816f(cacc[nt * 4 + 1], ef[kk][nt], w0[2], w0[3]);
                mma16816f(cacc[nt * 4 + 2], ef[kk][nt], w1[0], w1[1]);
                mma16816f(cacc[nt * 4 + 3], ef[kk][nt], w1[2], w1[3]);
            }
        }

        // scale by 1/sum and stage transposed: stg[h_local][n]
#pragma unroll
        for (int nt = 0; nt < 2; nt++)
#pragma unroll
            for (int u = 0; u < 4; u++) {
                float* A = cacc[nt * 4 + u];
                int hcl = hb + (u >> 1) * 16 + (u & 1) * 8 + 2 * qq;
                int n   = nb + nt * 16 + rr;
                stg[(size_t)hcl * STGS + n]           = A[0] * rc[nt][0];
                stg[(size_t)(hcl + 1) * STGS + n]     = A[1] * rc[nt][0];
                stg[(size_t)hcl * STGS + n + 8]       = A[2] * rc[nt][1];
                stg[(size_t)(hcl + 1) * STGS + n + 8] = A[3] * rc[nt][1];
            }
        __syncthreads();                 // stage writes visible

        // coalesced fp32 store: out[b][hc2*64+hr][n0 + ...]
#pragma unroll
        for (int it = 0; it < 8; it++) {
            int f = it * 128 + tid, hr = f >> 4, n4 = (f & 15) << 2;
            float4 v = *(const float4*)(stg + (size_t)hr * STGS + n4);
            *(float4*)(outb + (size_t)(hc2 * 64 + hr) * NDIM + n0 + n4) = v;
        }
        // STG reuse protected by the next chunk's top __syncthreads()
    }
}

// ============================================================
extern "C" void kernel_launch(void* const* d_in, const int* in_sizes, int n_in,
                              void* d_out, int out_size) {
    const float* H      = (const float*)d_in[0];  // [32,512,64,64]
    const float* W      = (const float*)d_in[1];  // [32,256,128]
    const float* head_w = (const float*)d_in[2];  // [512,256]
    float* out = (float*)d_out;

    cudaFuncSetAttribute(proj_kernel,
                         cudaFuncAttributeMaxDynamicSharedMemorySize, PSMEM);
    cudaFuncSetAttribute(attn_kernel,
                         cudaFuncAttributeMaxDynamicSharedMemorySize, SMEM_DYN);

    proj_kernel<<<dim3(4, B_DIM), 256, PSMEM>>>(W, head_w);
    attn_kernel<<<dim3(NDIM / 64, B_DIM), 128, SMEM_DYN>>>(H, out);
}

// round 16
// speedup vs baseline: 1.0261x; 1.0261x over previous
#include <cuda_runtime.h>
#include <cuda_bf16.h>
#include <cuda_fp16.h>
#include <cstdint>
#include <cstddef>

#define B_DIM 32
#define HDIM  512
#define NDIM  4096
#define MDIM  128
#define TDIM  256

// __device__ scratch. WpT bf16 hi/lo (GEMM1, 3-split); Wp single fp16 (GEMM2).
__device__ __align__(16) __nv_bfloat16 g_WpT_hi[B_DIM * MDIM * HDIM]; // [b][m][h]
__device__ __align__(16) __nv_bfloat16 g_WpT_lo[B_DIM * MDIM * HDIM];
__device__ __align__(16) __half        g_Wp_f16[B_DIM * HDIM * MDIM]; // [b][h][m]

// ---------------- helpers (all non-arch-specific PTX) ----------------
__device__ __forceinline__ uint32_t smem_u32(const void* p) {
    uint32_t a;
    asm("{ .reg .u64 t; cvta.to.shared.u64 t, %1; cvt.u32.u64 %0, t; }"
        : "=r"(a) : "l"(p));
    return a;
}
__device__ __forceinline__ void ldsm4(uint32_t* r, uint32_t a) {
    asm volatile("ldmatrix.sync.aligned.m8n8.x4.shared.b16 {%0,%1,%2,%3}, [%4];"
        : "=r"(r[0]), "=r"(r[1]), "=r"(r[2]), "=r"(r[3]) : "r"(a));
}
__device__ __forceinline__ void ldsm4t(uint32_t* r, uint32_t a) {
    asm volatile("ldmatrix.sync.aligned.m8n8.x4.trans.shared.b16 {%0,%1,%2,%3}, [%4];"
        : "=r"(r[0]), "=r"(r[1]), "=r"(r[2]), "=r"(r[3]) : "r"(a));
}
__device__ __forceinline__ void mma16816(float* d, const uint32_t* a,
                                         uint32_t b0, uint32_t b1) {
    asm volatile(
        "mma.sync.aligned.m16n8k16.row.col.f32.bf16.bf16.f32 "
        "{%0,%1,%2,%3}, {%4,%5,%6,%7}, {%8,%9}, {%0,%1,%2,%3};"
        : "+f"(d[0]), "+f"(d[1]), "+f"(d[2]), "+f"(d[3])
        : "r"(a[0]), "r"(a[1]), "r"(a[2]), "r"(a[3]), "r"(b0), "r"(b1));
}
__device__ __forceinline__ void mma16816f(float* d, const uint32_t* a,
                                          uint32_t b0, uint32_t b1) {
    asm volatile(
        "mma.sync.aligned.m16n8k16.row.col.f32.f16.f16.f32 "
        "{%0,%1,%2,%3}, {%4,%5,%6,%7}, {%8,%9}, {%0,%1,%2,%3};"
        : "+f"(d[0]), "+f"(d[1]), "+f"(d[2]), "+f"(d[3])
        : "r"(a[0]), "r"(a[1]), "r"(a[2]), "r"(a[3]), "r"(b0), "r"(b1));
}
__device__ __forceinline__ void split2(float x, float y, uint32_t& hi, uint32_t& lo) {
    __nv_bfloat16 xh = __float2bfloat16(x);
    __nv_bfloat16 yh = __float2bfloat16(y);
    __nv_bfloat16 xl = __float2bfloat16(x - __bfloat162float(xh));
    __nv_bfloat16 yl = __float2bfloat16(y - __bfloat162float(yh));
    hi = (uint32_t)__bfloat16_as_ushort(xh) | ((uint32_t)__bfloat16_as_ushort(yh) << 16);
    lo = (uint32_t)__bfloat16_as_ushort(xl) | ((uint32_t)__bfloat16_as_ushort(yl) << 16);
}
__device__ __forceinline__ uint32_t packh2(float x, float y) {
    __half2 h = __floats2half2_rn(x, y);
    return *(uint32_t*)&h;
}
// streaming store (evict-first): output is write-once, never re-read
__device__ __forceinline__ void stcs4(float* p, float4 v) {
    asm volatile("st.global.cs.v4.f32 [%0], {%1,%2,%3,%4};"
                 :: "l"(p), "f"(v.x), "f"(v.y), "f"(v.z), "f"(v.w) : "memory");
}
#define CP_ASYNC16(dst, src)                                                   \
    asm volatile("cp.async.cg.shared.global [%0], [%1], 16;"                   \
                 :: "r"(dst), "l"(src))
#define CP_COMMIT() asm volatile("cp.async.commit_group;" ::: "memory")
#define CP_WAIT(n)  asm volatile("cp.async.wait_group %0;" :: "n"(n) : "memory")

// ============================================================
// Kernel 1 (unchanged, proven): WpT bf16 hi/lo + Wp fp16 via 3-split MMA.
// ============================================================
#define PPADA 136
#define PPADB 40
#define PSTG  133
#define POFF_A  0
#define PA_HALF 8704
#define POFF_B  17408
#define PB_HALF 10240
#define PSMEM   69632

__global__ __launch_bounds__(256) void proj_kernel(const float* __restrict__ W,
                                                   const float* __restrict__ head_w) {
    extern __shared__ char smem[];
    const uint32_t sbase = smem_u32(smem);

    const int tid = threadIdx.x;
    const int wid = tid >> 5;
    const int lid = tid & 31;
    const int b   = blockIdx.y;
    const int h0  = blockIdx.x * 128;

    const float* Wb = W + (size_t)b * TDIM * MDIM;

    const int g  = lid >> 3, lr = lid & 7;
    const int arow = ((g & 2) ? 8 : 0) + lr;
    const int acol = wid * 16 + ((g & 1) ? 8 : 0);
    const uint32_t a_off = (uint32_t)(arow * PPADA + acol) * 2;
    const int brow = ((g >> 1) ? 8 : 0) + lr;
    const int bcol = (g & 1) ? 8 : 0;
    const uint32_t b_off = (uint32_t)(brow * PPADB + bcol) * 2;

    float4 ra[4], rb[4];
    auto ldg_chunk = [&](int kc) {
#pragma unroll
        for (int it = 0; it < 4; it++) {
            int fa = it * 256 + tid;
            int ar = fa >> 5, ac4 = (fa & 31) << 2;
            ra[it] = *(const float4*)(Wb + (size_t)(kc * 32 + ar) * MDIM + ac4);
            int br = fa >> 3, bc4 = (fa & 7) << 2;
            rb[it] = *(const float4*)(head_w + (size_t)(h0 + br) * TDIM + kc * 32 + bc4);
        }
    };
    auto conv_chunk = [&]() {
#pragma unroll
        for (int it = 0; it < 4; it++) {
            int fa = it * 256 + tid;
            int ar = fa >> 5, ac4 = (fa & 31) << 2;
            uint32_t h01, l01, h23, l23;
            split2(ra[it].x, ra[it].y, h01, l01);
            split2(ra[it].z, ra[it].w, h23, l23);
            uint32_t off = (uint32_t)(ar * PPADA + ac4) * 2;
            *(uint2*)(smem + POFF_A + off)            = make_uint2(h01, h23);
            *(uint2*)(smem + POFF_A + PA_HALF + off)  = make_uint2(l01, l23);
            int br = fa >> 3, bc4 = (fa & 7) << 2;
            split2(rb[it].x, rb[it].y, h01, l01);
            split2(rb[it].z, rb[it].w, h23, l23);
            off = (uint32_t)(br * PPADB + bc4) * 2;
            *(uint2*)(smem + POFF_B + off)            = make_uint2(h01, h23);
            *(uint2*)(smem + POFF_B + PB_HALF + off)  = make_uint2(l01, l23);
        }
    };

    float sacc[16][4];
#pragma unroll
    for (int t = 0; t < 16; t++)
#pragma unroll
        for (int j = 0; j < 4; j++) sacc[t][j] = 0.f;

    ldg_chunk(0);
    for (int kc = 0; kc < 8; kc++) {
        conv_chunk();
        __syncthreads();
        if (kc < 7) ldg_chunk(kc + 1);

        const uint32_t ahi = sbase + POFF_A, alo = ahi + PA_HALF;
        const uint32_t bhi = sbase + POFF_B, blo = bhi + PB_HALF;
#pragma unroll
        for (int kk = 0; kk < 2; kk++) {
            uint32_t ah[4], al[4];
            uint32_t aoff = a_off + (uint32_t)(kk * 16 * PPADA) * 2;
            ldsm4t(ah, ahi + aoff);
            ldsm4t(al, alo + aoff);
#pragma unroll
            for (int pr = 0; pr < 4; pr++) {
                uint32_t bh0[4], bl0[4], bh1[4], bl1[4];
                uint32_t bo0 = b_off + (uint32_t)((2 * pr) * 16 * PPADB + kk * 16) * 2;
                uint32_t bo1 = b_off + (uint32_t)((2 * pr + 1) * 16 * PPADB + kk * 16) * 2;
                ldsm4(bh0, bhi + bo0);
                ldsm4(bh1, bhi + bo1);
                ldsm4(bl0, blo + bo0);
                ldsm4(bl1, blo + bo1);
                float* A0 = sacc[4 * pr + 0];
                float* A1 = sacc[4 * pr + 1];
                float* A2 = sacc[4 * pr + 2];
                float* A3 = sacc[4 * pr + 3];
                mma16816(A0, ah, bh0[0], bh0[1]);
                mma16816(A1, ah, bh0[2], bh0[3]);
                mma16816(A2, ah, bh1[0], bh1[1]);
                mma16816(A3, ah, bh1[2], bh1[3]);
                mma16816(A0, ah, bl0[0], bl0[1]);
                mma16816(A1, ah, bl0[2], bl0[3]);
                mma16816(A2, ah, bl1[0], bl1[1]);
                mma16816(A3, ah, bl1[2], bl1[3]);
                mma16816(A0, al, bh0[0], bh0[1]);
                mma16816(A1, al, bh0[2], bh0[3]);
                mma16816(A2, al, bh1[0], bh1[1]);
                mma16816(A3, al, bh1[2], bh1[3]);
            }
        }
        __syncthreads();
    }

    float* stg = (float*)smem;
    const int rr = lid >> 2, qq = lid & 3;
#pragma unroll
    for (int t = 0; t < 16; t++) {
        int hcl = t * 8 + 2 * qq;
        int m   = wid * 16 + rr;
        stg[(size_t)m * PSTG + hcl]           = sacc[t][0];
        stg[(size_t)m * PSTG + hcl + 1]       = sacc[t][1];
        stg[(size_t)(m + 8) * PSTG + hcl]     = sacc[t][2];
        stg[(size_t)(m + 8) * PSTG + hcl + 1] = sacc[t][3];
    }
    __syncthreads();

#pragma unroll
    for (int it = 0; it < 16; it++) {
        int f = it * 256 + tid;
        int m = f >> 5, c4 = (f & 31) << 2;
        const float* s = stg + (size_t)m * PSTG + c4;
        uint32_t h01, l01, h23, l23;
        split2(s[0], s[1], h01, l01);
        split2(s[2], s[3], h23, l23);
        size_t base = ((size_t)b * MDIM + m) * HDIM + h0 + c4;
        *(uint2*)(g_WpT_hi + base) = make_uint2(h01, h23);
        *(uint2*)(g_WpT_lo + base) = make_uint2(l01, l23);
    }
#pragma unroll
    for (int it = 0; it < 16; it++) {
        int f = it * 256 + tid;
        int h = f >> 5, m4 = (f & 31) << 2;
        float x0 = stg[(size_t)(m4 + 0) * PSTG + h];
        float x1 = stg[(size_t)(m4 + 1) * PSTG + h];
        float x2 = stg[(size_t)(m4 + 2) * PSTG + h];
        float x3 = stg[(size_t)(m4 + 3) * PSTG + h];
        uint32_t p01 = packh2(x0, x1), p23 = packh2(x2, x3);
        size_t base = ((size_t)b * HDIM + h0 + h) * MDIM + m4;
        *(uint2*)(g_Wp_f16 + base) = make_uint2(p01, p23);
    }
}

// ============================================================
// Kernel 2 (R14 structure, GEMM2 reverted to n-split): GEMM1 m-split,
// softmax cross-warp m-reduction, E smem roundtrip, GEMM2 n-split,
// 4 CTAs/SM. Output stores use st.global.cs (streaming).
// ============================================================
#define PADQ 72
#define PADK 40
#define PADW 136
#define PADE 136
#define STGS 68
#define OFF_KB  0
#define KB_SZ   20480
#define OFF_Q   40960
#define OFF_WB  0
#define WB_SZ   17408
#define OFF_E   34816
#define OFF_STG 34816
#define OFF_RCP 52224
#define SMEM_DYN 52480

__global__ __launch_bounds__(128, 4)
void attn_kernel(const float* __restrict__ H, float* __restrict__ out) {
    extern __shared__ char smem[];
    const uint32_t sbase = smem_u32(smem);

    const int tid = threadIdx.x;
    const int wid = tid >> 5;
    const int lid = tid & 31;
    const int b   = blockIdx.y;
    const int n0  = blockIdx.x * 64;

    const float* Hb = H + (size_t)b * HDIM * NDIM + n0;
    const __nv_bfloat16* KTh = g_WpT_hi + (size_t)b * MDIM * HDIM;
    const __nv_bfloat16* KTl = g_WpT_lo + (size_t)b * MDIM * HDIM;
    const __half*        Wpf = g_Wp_f16 + (size_t)b * HDIM * MDIM;

    const int g  = lid >> 3, lr = lid & 7;
    const int rr = lid >> 2, qq = lid & 3;
    const int arow_k = ((g & 2) ? 8 : 0) + lr;
    const int acq    = (g & 1) ? 8 : 0;
    const int brow_m = ((g >> 1) ? 8 : 0) + lr;
    const int bcq    = (g & 1) ? 8 : 0;
    const uint32_t b_off_w = (uint32_t)(brow_m * PADW + bcq) * 2;
    const int earow = ((g & 1) ? 8 : 0) + lr;
    const uint32_t e_off = (uint32_t)((16 * wid + earow) * (PADE * 2) + ((g & 2) ? 16 : 0));

    auto issue_k = [&](int hc, int p) {
        uint32_t dh = sbase + OFF_KB + p * KB_SZ;
        uint32_t dl = dh + 10240;
        int k0 = hc * 32;
#pragma unroll
        for (int it = 0; it < 4; it++) {
            int f = it * 128 + tid, m = f >> 2, c8 = (f & 3) << 3;
            uint32_t o = (uint32_t)(m * PADK + c8) * 2;
            CP_ASYNC16(dh + o, KTh + (size_t)m * HDIM + k0 + c8);
            CP_ASYNC16(dl + o, KTl + (size_t)m * HDIM + k0 + c8);
        }
    };
    auto issue_w = [&](int hc2, int p) {
        uint32_t dw = sbase + OFF_WB + p * WB_SZ;
#pragma unroll
        for (int it = 0; it < 8; it++) {
            int f = it * 128 + tid, hr = f >> 4, c8 = (f & 15) << 3;
            uint32_t o = (uint32_t)(hr * PADW + c8) * 2;
            CP_ASYNC16(dw + o, Wpf + (size_t)(hc2 * 64 + hr) * MDIM + c8);
        }
    };
    auto ldg_q = [&](int hc, float4* qv) {
#pragma unroll
        for (int it = 0; it < 4; it++) {
            int f = it * 128 + tid, hr = f >> 4, c4 = (f & 15) << 2;
            qv[it] = *(const float4*)(Hb + (size_t)(hc * 32 + hr) * NDIM + c4);
        }
    };
    auto conv_q = [&](const float4* qv) {
#pragma unroll
        for (int it = 0; it < 4; it++) {
            int f = it * 128 + tid, hr = f >> 4, c4 = (f & 15) << 2;
            uint32_t h01, l01, h23, l23;
            split2(qv[it].x, qv[it].y, h01, l01);
            split2(qv[it].z, qv[it].w, h23, l23);
            uint32_t off = (uint32_t)(hr * PADQ + c4) * 2;
            *(uint2*)(smem + OFF_Q + off)        = make_uint2(h01, h23);
            *(uint2*)(smem + OFF_Q + 4608 + off) = make_uint2(l01, l23);
        }
    };

    // ------ GEMM1 (m-split, identical to R14) ------
    float sacc[16][4];
#pragma unroll
    for (int t = 0; t < 16; t++)
#pragma unroll
        for (int j = 0; j < 4; j++) sacc[t][j] = 0.f;

    float4 qv[4];
    issue_k(0, 0); CP_COMMIT();
    ldg_q(0, qv);
    conv_q(qv);
    ldg_q(1, qv);

    const uint32_t qhi = sbase + OFF_Q;
    const uint32_t qlo = qhi + 4608;

    for (int hc = 0; hc < 16; hc++) {
        const int p = hc & 1;
        CP_WAIT(0);
        __syncthreads();
        if (hc < 15) { issue_k(hc + 1, p ^ 1); CP_COMMIT(); }

        const uint32_t khi = sbase + OFF_KB + p * KB_SZ;
        const uint32_t klo = khi + 10240;
#pragma unroll
        for (int kk = 0; kk < 2; kk++) {
            uint32_t bh0[4], bl0[4], bh1[4], bl1[4];
            uint32_t bo0 = (uint32_t)((32 * wid + brow_m) * PADK + bcq + kk * 16) * 2;
            uint32_t bo1 = bo0 + (uint32_t)(16 * PADK) * 2;
            ldsm4(bh0, khi + bo0);
            ldsm4(bh1, khi + bo1);
            ldsm4(bl0, klo + bo0);
            ldsm4(bl1, klo + bo1);
#pragma unroll
            for (int nt = 0; nt < 4; nt++) {
                uint32_t ah[4], al[4];
                uint32_t ao = (uint32_t)((arow_k + kk * 16) * PADQ + nt * 16 + acq) * 2;
                ldsm4t(ah, qhi + ao);
                ldsm4t(al, qlo + ao);
                float* A0 = sacc[nt * 4 + 0];
                float* A1 = sacc[nt * 4 + 1];
                float* A2 = sacc[nt * 4 + 2];
                float* A3 = sacc[nt * 4 + 3];
                mma16816(A0, ah, bh0[0], bh0[1]);
                mma16816(A1, ah, bh0[2], bh0[3]);
                mma16816(A2, ah, bh1[0], bh1[1]);
                mma16816(A3, ah, bh1[2], bh1[3]);
                mma16816(A0, ah, bl0[0], bl0[1]);
                mma16816(A1, ah, bl0[2], bl0[3]);
                mma16816(A2, ah, bl1[0], bl1[1]);
                mma16816(A3, ah, bl1[2], bl1[3]);
                mma16816(A0, al, bh0[0], bh0[1]);
                mma16816(A1, al, bh0[2], bh0[3]);
                mma16816(A2, al, bh1[0], bh1[1]);
                mma16816(A3, al, bh1[2], bh1[3]);
            }
        }
        __syncthreads();
        if (hc < 15) conv_q(qv);
        if (hc < 14) ldg_q(hc + 2, qv);
    }

    // prefetch GEMM2 chunk 0 (WB0 aliases dead KB0)
    issue_w(0, 0); CP_COMMIT();

    // ---------------- softmax over m (cross-warp m-reduction) ----------------
    float* pm = (float*)(smem + OFF_E);          // [4 warps][64 n]
    float* ps = (float*)(smem + OFF_E + 1024);   // [4 warps][64 n]
    float* rcp = (float*)(smem + OFF_RCP);       // [64 n]

    float mx[4][2];
#pragma unroll
    for (int nt = 0; nt < 4; nt++) { mx[nt][0] = -3.4e38f; mx[nt][1] = -3.4e38f; }
#pragma unroll
    for (int t = 0; t < 16; t++) {
        int nt = t >> 2;
        mx[nt][0] = fmaxf(mx[nt][0], fmaxf(sacc[t][0], sacc[t][1]));
        mx[nt][1] = fmaxf(mx[nt][1], fmaxf(sacc[t][2], sacc[t][3]));
    }
#pragma unroll
    for (int nt = 0; nt < 4; nt++)
#pragma unroll
        for (int hf = 0; hf < 2; hf++) {
            mx[nt][hf] = fmaxf(mx[nt][hf], __shfl_xor_sync(0xFFFFFFFFu, mx[nt][hf], 1));
            mx[nt][hf] = fmaxf(mx[nt][hf], __shfl_xor_sync(0xFFFFFFFFu, mx[nt][hf], 2));
        }
    if (qq == 0) {
#pragma unroll
        for (int nt = 0; nt < 4; nt++)
#pragma unroll
            for (int hf = 0; hf < 2; hf++)
                pm[wid * 64 + nt * 16 + hf * 8 + rr] = mx[nt][hf];
    }
    __syncthreads();
    float rmax[4][2];
#pragma unroll
    for (int nt = 0; nt < 4; nt++)
#pragma unroll
        for (int hf = 0; hf < 2; hf++) {
            int n = nt * 16 + hf * 8 + rr;
            float v = fmaxf(pm[n], pm[64 + n]);
            v = fmaxf(v, fmaxf(pm[128 + n], pm[192 + n]));
            rmax[nt][hf] = v;
        }
    float sm[4][2];
#pragma unroll
    for (int nt = 0; nt < 4; nt++) { sm[nt][0] = 0.f; sm[nt][1] = 0.f; }
#pragma unroll
    for (int t = 0; t < 16; t++) {
        int nt = t >> 2;
        sacc[t][0] = __expf(sacc[t][0] - rmax[nt][0]);
        sacc[t][1] = __expf(sacc[t][1] - rmax[nt][0]);
        sacc[t][2] = __expf(sacc[t][2] - rmax[nt][1]);
        sacc[t][3] = __expf(sacc[t][3] - rmax[nt][1]);
        sm[nt][0] += sacc[t][0] + sacc[t][1];
        sm[nt][1] += sacc[t][2] + sacc[t][3];
    }
#pragma unroll
    for (int nt = 0; nt < 4; nt++)
#pragma unroll
        for (int hf = 0; hf < 2; hf++) {
            sm[nt][hf] += __shfl_xor_sync(0xFFFFFFFFu, sm[nt][hf], 1);
            sm[nt][hf] += __shfl_xor_sync(0xFFFFFFFFu, sm[nt][hf], 2);
        }
    if (qq == 0) {
#pragma unroll
        for (int nt = 0; nt < 4; nt++)
#pragma unroll
            for (int hf = 0; hf < 2; hf++)
                ps[wid * 64 + nt * 16 + hf * 8 + rr] = sm[nt][hf];
    }
    __syncthreads();
    if (wid == 0 && qq == 0) {
#pragma unroll
        for (int nt = 0; nt < 4; nt++)
#pragma unroll
            for (int hf = 0; hf < 2; hf++) {
                int n = nt * 16 + hf * 8 + rr;
                rcp[n] = 1.0f / (ps[n] + ps[64 + n] + ps[128 + n] + ps[192 + n]);
            }
    }
    __syncthreads();   // all ps/pm reads done; E may overwrite the area

    // ---- write unnormalized E (fp16) to smem [n64][m128], stride PADE ----
#pragma unroll
    for (int t = 0; t < 16; t++) {
        int nt = t >> 2, u = t & 3;
        int m  = 32 * wid + (u >> 1) * 16 + (u & 1) * 8 + 2 * qq;
        int nr = nt * 16 + rr;
        *(uint32_t*)(smem + OFF_E + (size_t)nr * (PADE * 2) + m * 2) =
            packh2(sacc[t][0], sacc[t][1]);
        *(uint32_t*)(smem + OFF_E + (size_t)(nr + 8) * (PADE * 2) + m * 2) =
            packh2(sacc[t][2], sacc[t][3]);
    }
    __syncthreads();

    // ---- reload E as GEMM2 A-fragments (n-split: warp w owns n16 slice) ----
    uint32_t ef[8][4];
#pragma unroll
    for (int kk = 0; kk < 8; kk++)
        ldsm4(ef[kk], sbase + OFF_E + e_off + kk * 32);
    const float r0 = ((float*)(smem + OFF_RCP))[16 * wid + rr];
    const float r1 = ((float*)(smem + OFF_RCP))[16 * wid + rr + 8];

    // -------- GEMM2 (n-split, as R14): C[n][h] = sum_m E[n][m]*Wp[h][m] --------
    float* outb = out + (size_t)b * HDIM * NDIM;
    float* stg = (float*)(smem + OFF_STG);

    for (int hc2 = 0; hc2 < 8; hc2++) {
        const int p = hc2 & 1;
        CP_WAIT(0);
        __syncthreads();                 // WB[p] visible; STG free (ef loaded)
        if (hc2 < 7) { issue_w(hc2 + 1, p ^ 1); CP_COMMIT(); }

        float cacc[8][4];
#pragma unroll
        for (int t = 0; t < 8; t++)
#pragma unroll
            for (int j = 0; j < 4; j++) cacc[t][j] = 0.f;

        const uint32_t wb = sbase + OFF_WB + p * WB_SZ;
#pragma unroll
        for (int kk = 0; kk < 8; kk++) {
            uint32_t b0[4], b1[4], b2[4], b3[4];
            uint32_t ko = (uint32_t)(kk * 16) * 2;
            ldsm4(b0, wb + b_off_w + ko);
            ldsm4(b1, wb + b_off_w + (uint32_t)(16 * PADW) * 2 + ko);
            ldsm4(b2, wb + b_off_w + (uint32_t)(32 * PADW) * 2 + ko);
            ldsm4(b3, wb + b_off_w + (uint32_t)(48 * PADW) * 2 + ko);
            mma16816f(cacc[0], ef[kk], b0[0], b0[1]);
            mma16816f(cacc[1], ef[kk], b0[2], b0[3]);
            mma16816f(cacc[2], ef[kk], b1[0], b1[1]);
            mma16816f(cacc[3], ef[kk], b1[2], b1[3]);
            mma16816f(cacc[4], ef[kk], b2[0], b2[1]);
            mma16816f(cacc[5], ef[kk], b2[2], b2[3]);
            mma16816f(cacc[6], ef[kk], b3[0], b3[1]);
            mma16816f(cacc[7], ef[kk], b3[2], b3[3]);
        }

        // scale by 1/sum and stage transposed: stg[h_local][n]
#pragma unroll
        for (int t = 0; t < 8; t++) {
            int hcl = t * 8 + 2 * qq;
            int n   = wid * 16 + rr;
            stg[(size_t)hcl * STGS + n]           = cacc[t][0] * r0;
            stg[(size_t)(hcl + 1) * STGS + n]     = cacc[t][1] * r0;
            stg[(size_t)hcl * STGS + n + 8]       = cacc[t][2] * r1;
            stg[(size_t)(hcl + 1) * STGS + n + 8] = cacc[t][3] * r1;
        }
        __syncthreads();                 // stage writes visible

        // streaming fp32 store: out[b][hc2*64+hr][n0 + ...]
#pragma unroll
        for (int it = 0; it < 8; it++) {
            int f = it * 128 + tid, hr = f >> 4, n4 = (f & 15) << 2;
            float4 v = *(const float4*)(stg + (size_t)hr * STGS + n4);
            stcs4(outb + (size_t)(hc2 * 64 + hr) * NDIM + n0 + n4, v);
        }
        // STG reuse protected by the next chunk's top __syncthreads()
    }
}

// ============================================================
extern "C" void kernel_launch(void* const* d_in, const int* in_sizes, int n_in,
                              void* d_out, int out_size) {
    const float* H      = (const float*)d_in[0];  // [32,512,64,64]
    const float* W      = (const float*)d_in[1];  // [32,256,128]
    const float* head_w = (const float*)d_in[2];  // [512,256]
    float* out = (float*)d_out;

    cudaFuncSetAttribute(proj_kernel,
                         cudaFuncAttributeMaxDynamicSharedMemorySize, PSMEM);
    cudaFuncSetAttribute(attn_kernel,
                         cudaFuncAttributeMaxDynamicSharedMemorySize, SMEM_DYN);

    proj_kernel<<<dim3(4, B_DIM), 256, PSMEM>>>(W, head_w);
    attn_kernel<<<dim3(NDIM / 64, B_DIM), 128, SMEM_DYN>>>(H, out);
}

// round 17
// speedup vs baseline: 1.0300x; 1.0039x over previous
#include <cuda_runtime.h>
#include <cuda_bf16.h>
#include <cuda_fp16.h>
#include <cstdint>
#include <cstddef>

#define B_DIM 32
#define HDIM  512
#define NDIM  4096
#define MDIM  128
#define TDIM  256

// __device__ scratch. WpT bf16 hi/lo (GEMM1, 3-split); Wp single fp16 (GEMM2).
__device__ __align__(16) __nv_bfloat16 g_WpT_hi[B_DIM * MDIM * HDIM]; // [b][m][h]
__device__ __align__(16) __nv_bfloat16 g_WpT_lo[B_DIM * MDIM * HDIM];
__device__ __align__(16) __half        g_Wp_f16[B_DIM * HDIM * MDIM]; // [b][h][m]

// ---------------- helpers (all non-arch-specific PTX) ----------------
__device__ __forceinline__ uint32_t smem_u32(const void* p) {
    uint32_t a;
    asm("{ .reg .u64 t; cvta.to.shared.u64 t, %1; cvt.u32.u64 %0, t; }"
        : "=r"(a) : "l"(p));
    return a;
}
__device__ __forceinline__ void ldsm4(uint32_t* r, uint32_t a) {
    asm volatile("ldmatrix.sync.aligned.m8n8.x4.shared.b16 {%0,%1,%2,%3}, [%4];"
        : "=r"(r[0]), "=r"(r[1]), "=r"(r[2]), "=r"(r[3]) : "r"(a));
}
__device__ __forceinline__ void ldsm4t(uint32_t* r, uint32_t a) {
    asm volatile("ldmatrix.sync.aligned.m8n8.x4.trans.shared.b16 {%0,%1,%2,%3}, [%4];"
        : "=r"(r[0]), "=r"(r[1]), "=r"(r[2]), "=r"(r[3]) : "r"(a));
}
__device__ __forceinline__ void mma16816(float* d, const uint32_t* a,
                                         uint32_t b0, uint32_t b1) {
    asm volatile(
        "mma.sync.aligned.m16n8k16.row.col.f32.bf16.bf16.f32 "
        "{%0,%1,%2,%3}, {%4,%5,%6,%7}, {%8,%9}, {%0,%1,%2,%3};"
        : "+f"(d[0]), "+f"(d[1]), "+f"(d[2]), "+f"(d[3])
        : "r"(a[0]), "r"(a[1]), "r"(a[2]), "r"(a[3]), "r"(b0), "r"(b1));
}
__device__ __forceinline__ void mma16816f(float* d, const uint32_t* a,
                                          uint32_t b0, uint32_t b1) {
    asm volatile(
        "mma.sync.aligned.m16n8k16.row.col.f32.f16.f16.f32 "
        "{%0,%1,%2,%3}, {%4,%5,%6,%7}, {%8,%9}, {%0,%1,%2,%3};"
        : "+f"(d[0]), "+f"(d[1]), "+f"(d[2]), "+f"(d[3])
        : "r"(a[0]), "r"(a[1]), "r"(a[2]), "r"(a[3]), "r"(b0), "r"(b1));
}
__device__ __forceinline__ void split2(float x, float y, uint32_t& hi, uint32_t& lo) {
    __nv_bfloat16 xh = __float2bfloat16(x);
    __nv_bfloat16 yh = __float2bfloat16(y);
    __nv_bfloat16 xl = __float2bfloat16(x - __bfloat162float(xh));
    __nv_bfloat16 yl = __float2bfloat16(y - __bfloat162float(yh));
    hi = (uint32_t)__bfloat16_as_ushort(xh) | ((uint32_t)__bfloat16_as_ushort(yh) << 16);
    lo = (uint32_t)__bfloat16_as_ushort(xl) | ((uint32_t)__bfloat16_as_ushort(yl) << 16);
}
__device__ __forceinline__ uint32_t packh2(float x, float y) {
    __half2 h = __floats2half2_rn(x, y);
    return *(uint32_t*)&h;
}
// streaming store (evict-first): output is write-once, never re-read
__device__ __forceinline__ void stcs4(float* p, float4 v) {
    asm volatile("st.global.cs.v4.f32 [%0], {%1,%2,%3,%4};"
                 :: "l"(p), "f"(v.x), "f"(v.y), "f"(v.z), "f"(v.w) : "memory");
}
#define CP_ASYNC16(dst, src)                                                   \
    asm volatile("cp.async.cg.shared.global [%0], [%1], 16;"                   \
                 :: "r"(dst), "l"(src))
#define CP_COMMIT() asm volatile("cp.async.commit_group;" ::: "memory")
#define CP_WAIT(n)  asm volatile("cp.async.wait_group %0;" :: "n"(n) : "memory")

// ============================================================
// Kernel 1: WpT bf16 hi/lo + Wp fp16 via 3-split MMA.
// NOW h-slice 64: grid (8, 32), halved per-CTA work (384 MMA/warp).
// Accumulation order per element unchanged -> bit-identical output.
//   D[m][h] = sum_t W[b][t][m] * head_w[h0+h][t],  h0 = bx*64
// ============================================================
#define PPADA 136
#define PPADB 40
#define PSTG  133
#define POFF_A  0
#define PA_HALF 8704          // 32*136*2
#define POFF_B  17408
#define PB_HALF 5120          // 64*40*2
#define PSMEM   36352         // stage 128*69*4 = 35328 aliases tiles

__global__ __launch_bounds__(256) void proj_kernel(const float* __restrict__ W,
                                                   const float* __restrict__ head_w) {
    extern __shared__ char smem[];
    const uint32_t sbase = smem_u32(smem);

    const int tid = threadIdx.x;
    const int wid = tid >> 5;
    const int lid = tid & 31;
    const int b   = blockIdx.y;
    const int h0  = blockIdx.x * 64;

    const float* Wb = W + (size_t)b * TDIM * MDIM;

    const int g  = lid >> 3, lr = lid & 7;
    const int arow = ((g & 2) ? 8 : 0) + lr;
    const int acol = wid * 16 + ((g & 1) ? 8 : 0);
    const uint32_t a_off = (uint32_t)(arow * PPADA + acol) * 2;
    const int brow = ((g >> 1) ? 8 : 0) + lr;
    const int bcol = (g & 1) ? 8 : 0;
    const uint32_t b_off = (uint32_t)(brow * PPADB + bcol) * 2;

    float4 ra[4], rb[2];
    auto ldg_chunk = [&](int kc) {
#pragma unroll
        for (int it = 0; it < 4; it++) {
            int fa = it * 256 + tid;
            int ar = fa >> 5, ac4 = (fa & 31) << 2;
            ra[it] = *(const float4*)(Wb + (size_t)(kc * 32 + ar) * MDIM + ac4);
        }
#pragma unroll
        for (int it = 0; it < 2; it++) {
            int fa = it * 256 + tid;
            int br = fa >> 3, bc4 = (fa & 7) << 2;
            rb[it] = *(const float4*)(head_w + (size_t)(h0 + br) * TDIM + kc * 32 + bc4);
        }
    };
    auto conv_chunk = [&]() {
#pragma unroll
        for (int it = 0; it < 4; it++) {
            int fa = it * 256 + tid;
            int ar = fa >> 5, ac4 = (fa & 31) << 2;
            uint32_t h01, l01, h23, l23;
            split2(ra[it].x, ra[it].y, h01, l01);
            split2(ra[it].z, ra[it].w, h23, l23);
            uint32_t off = (uint32_t)(ar * PPADA + ac4) * 2;
            *(uint2*)(smem + POFF_A + off)            = make_uint2(h01, h23);
            *(uint2*)(smem + POFF_A + PA_HALF + off)  = make_uint2(l01, l23);
        }
#pragma unroll
        for (int it = 0; it < 2; it++) {
            int fa = it * 256 + tid;
            int br = fa >> 3, bc4 = (fa & 7) << 2;
            uint32_t h01, l01, h23, l23;
            split2(rb[it].x, rb[it].y, h01, l01);
            split2(rb[it].z, rb[it].w, h23, l23);
            uint32_t off = (uint32_t)(br * PPADB + bc4) * 2;
            *(uint2*)(smem + POFF_B + off)            = make_uint2(h01, h23);
            *(uint2*)(smem + POFF_B + PB_HALF + off)  = make_uint2(l01, l23);
        }
    };

    float sacc[8][4];
#pragma unroll
    for (int t = 0; t < 8; t++)
#pragma unroll
        for (int j = 0; j < 4; j++) sacc[t][j] = 0.f;

    ldg_chunk(0);
    for (int kc = 0; kc < 8; kc++) {
        conv_chunk();
        __syncthreads();
        if (kc < 7) ldg_chunk(kc + 1);

        const uint32_t ahi = sbase + POFF_A, alo = ahi + PA_HALF;
        const uint32_t bhi = sbase + POFF_B, blo = bhi + PB_HALF;
#pragma unroll
        for (int kk = 0; kk < 2; kk++) {
            uint32_t ah[4], al[4];
            uint32_t aoff = a_off + (uint32_t)(kk * 16 * PPADA) * 2;
            ldsm4t(ah, ahi + aoff);
            ldsm4t(al, alo + aoff);
#pragma unroll
            for (int pr = 0; pr < 2; pr++) {
                uint32_t bh0[4], bl0[4], bh1[4], bl1[4];
                uint32_t bo0 = b_off + (uint32_t)((2 * pr) * 16 * PPADB + kk * 16) * 2;
                uint32_t bo1 = b_off + (uint32_t)((2 * pr + 1) * 16 * PPADB + kk * 16) * 2;
                ldsm4(bh0, bhi + bo0);
                ldsm4(bh1, bhi + bo1);
                ldsm4(bl0, blo + bo0);
                ldsm4(bl1, blo + bo1);
                float* A0 = sacc[4 * pr + 0];
                float* A1 = sacc[4 * pr + 1];
                float* A2 = sacc[4 * pr + 2];
                float* A3 = sacc[4 * pr + 3];
                mma16816(A0, ah, bh0[0], bh0[1]);
                mma16816(A1, ah, bh0[2], bh0[3]);
                mma16816(A2, ah, bh1[0], bh1[1]);
                mma16816(A3, ah, bh1[2], bh1[3]);
                mma16816(A0, ah, bl0[0], bl0[1]);
                mma16816(A1, ah, bl0[2], bl0[3]);
                mma16816(A2, ah, bl1[0], bl1[1]);
                mma16816(A3, ah, bl1[2], bl1[3]);
                mma16816(A0, al, bh0[0], bh0[1]);
                mma16816(A1, al, bh0[2], bh0[3]);
                mma16816(A2, al, bh1[0], bh1[1]);
                mma16816(A3, al, bh1[2], bh1[3]);
            }
        }
        __syncthreads();
    }

    // ---- epilogue: stage D[m128][h64] fp32 (stride 69), store both layouts ----
    float* stg = (float*)smem;
    const int rr = lid >> 2, qq = lid & 3;
#define PSTG2 69
#pragma unroll
    for (int t = 0; t < 8; t++) {
        int hcl = t * 8 + 2 * qq;
        int m   = wid * 16 + rr;
        stg[(size_t)m * PSTG2 + hcl]           = sacc[t][0];
        stg[(size_t)m * PSTG2 + hcl + 1]       = sacc[t][1];
        stg[(size_t)(m + 8) * PSTG2 + hcl]     = sacc[t][2];
        stg[(size_t)(m + 8) * PSTG2 + hcl + 1] = sacc[t][3];
    }
    __syncthreads();

    // WpT[b][m][h0+h] bf16 hi/lo: rows m, coalesced over h
#pragma unroll
    for (int it = 0; it < 8; it++) {
        int f = it * 256 + tid;          // 0..2047 groups of 4 h
        int m = f >> 4, c4 = (f & 15) << 2;
        const float* s = stg + (size_t)m * PSTG2 + c4;
        uint32_t h01, l01, h23, l23;
        split2(s[0], s[1], h01, l01);
        split2(s[2], s[3], h23, l23);
        size_t base = ((size_t)b * MDIM + m) * HDIM + h0 + c4;
        *(uint2*)(g_WpT_hi + base) = make_uint2(h01, h23);
        *(uint2*)(g_WpT_lo + base) = make_uint2(l01, l23);
    }
    // Wp[b][h0+h][m] single fp16: rows h, coalesced over m
#pragma unroll
    for (int it = 0; it < 8; it++) {
        int f = it * 256 + tid;          // 0..2047 groups of 4 m
        int h = f >> 5, m4 = (f & 31) << 2;
        float x0 = stg[(size_t)(m4 + 0) * PSTG2 + h];
        float x1 = stg[(size_t)(m4 + 1) * PSTG2 + h];
        float x2 = stg[(size_t)(m4 + 2) * PSTG2 + h];
        float x3 = stg[(size_t)(m4 + 3) * PSTG2 + h];
        uint32_t p01 = packh2(x0, x1), p23 = packh2(x2, x3);
        size_t base = ((size_t)b * HDIM + h0 + h) * MDIM + m4;
        *(uint2*)(g_Wp_f16 + base) = make_uint2(p01, p23);
    }
}

// ============================================================
// Kernel 2 (byte-identical to R16, the best attn config):
// GEMM1 m-split + softmax m-reduction + E roundtrip + GEMM2 n-split,
// 4 CTAs/SM, streaming output stores.
// ============================================================
#define PADQ 72
#define PADK 40
#define PADW 136
#define PADE 136
#define STGS 68
#define OFF_KB  0
#define KB_SZ   20480
#define OFF_Q   40960
#define OFF_WB  0
#define WB_SZ   17408
#define OFF_E   34816
#define OFF_STG 34816
#define OFF_RCP 52224
#define SMEM_DYN 52480

__global__ __launch_bounds__(128, 4)
void attn_kernel(const float* __restrict__ H, float* __restrict__ out) {
    extern __shared__ char smem[];
    const uint32_t sbase = smem_u32(smem);

    const int tid = threadIdx.x;
    const int wid = tid >> 5;
    const int lid = tid & 31;
    const int b   = blockIdx.y;
    const int n0  = blockIdx.x * 64;

    const float* Hb = H + (size_t)b * HDIM * NDIM + n0;
    const __nv_bfloat16* KTh = g_WpT_hi + (size_t)b * MDIM * HDIM;
    const __nv_bfloat16* KTl = g_WpT_lo + (size_t)b * MDIM * HDIM;
    const __half*        Wpf = g_Wp_f16 + (size_t)b * HDIM * MDIM;

    const int g  = lid >> 3, lr = lid & 7;
    const int rr = lid >> 2, qq = lid & 3;
    const int arow_k = ((g & 2) ? 8 : 0) + lr;
    const int acq    = (g & 1) ? 8 : 0;
    const int brow_m = ((g >> 1) ? 8 : 0) + lr;
    const int bcq    = (g & 1) ? 8 : 0;
    const uint32_t b_off_w = (uint32_t)(brow_m * PADW + bcq) * 2;
    const int earow = ((g & 1) ? 8 : 0) + lr;
    const uint32_t e_off = (uint32_t)((16 * wid + earow) * (PADE * 2) + ((g & 2) ? 16 : 0));

    auto issue_k = [&](int hc, int p) {
        uint32_t dh = sbase + OFF_KB + p * KB_SZ;
        uint32_t dl = dh + 10240;
        int k0 = hc * 32;
#pragma unroll
        for (int it = 0; it < 4; it++) {
            int f = it * 128 + tid, m = f >> 2, c8 = (f & 3) << 3;
            uint32_t o = (uint32_t)(m * PADK + c8) * 2;
            CP_ASYNC16(dh + o, KTh + (size_t)m * HDIM + k0 + c8);
            CP_ASYNC16(dl + o, KTl + (size_t)m * HDIM + k0 + c8);
        }
    };
    auto issue_w = [&](int hc2, int p) {
        uint32_t dw = sbase + OFF_WB + p * WB_SZ;
#pragma unroll
        for (int it = 0; it < 8; it++) {
            int f = it * 128 + tid, hr = f >> 4, c8 = (f & 15) << 3;
            uint32_t o = (uint32_t)(hr * PADW + c8) * 2;
            CP_ASYNC16(dw + o, Wpf + (size_t)(hc2 * 64 + hr) * MDIM + c8);
        }
    };
    auto ldg_q = [&](int hc, float4* qv) {
#pragma unroll
        for (int it = 0; it < 4; it++) {
            int f = it * 128 + tid, hr = f >> 4, c4 = (f & 15) << 2;
            qv[it] = *(const float4*)(Hb + (size_t)(hc * 32 + hr) * NDIM + c4);
        }
    };
    auto conv_q = [&](const float4* qv) {
#pragma unroll
        for (int it = 0; it < 4; it++) {
            int f = it * 128 + tid, hr = f >> 4, c4 = (f & 15) << 2;
            uint32_t h01, l01, h23, l23;
            split2(qv[it].x, qv[it].y, h01, l01);
            split2(qv[it].z, qv[it].w, h23, l23);
            uint32_t off = (uint32_t)(hr * PADQ + c4) * 2;
            *(uint2*)(smem + OFF_Q + off)        = make_uint2(h01, h23);
            *(uint2*)(smem + OFF_Q + 4608 + off) = make_uint2(l01, l23);
        }
    };

    // ------ GEMM1 (m-split) ------
    float sacc[16][4];
#pragma unroll
    for (int t = 0; t < 16; t++)
#pragma unroll
        for (int j = 0; j < 4; j++) sacc[t][j] = 0.f;

    float4 qv[4];
    issue_k(0, 0); CP_COMMIT();
    ldg_q(0, qv);
    conv_q(qv);
    ldg_q(1, qv);

    const uint32_t qhi = sbase + OFF_Q;
    const uint32_t qlo = qhi + 4608;

    for (int hc = 0; hc < 16; hc++) {
        const int p = hc & 1;
        CP_WAIT(0);
        __syncthreads();
        if (hc < 15) { issue_k(hc + 1, p ^ 1); CP_COMMIT(); }

        const uint32_t khi = sbase + OFF_KB + p * KB_SZ;
        const uint32_t klo = khi + 10240;
#pragma unroll
        for (int kk = 0; kk < 2; kk++) {
            uint32_t bh0[4], bl0[4], bh1[4], bl1[4];
            uint32_t bo0 = (uint32_t)((32 * wid + brow_m) * PADK + bcq + kk * 16) * 2;
            uint32_t bo1 = bo0 + (uint32_t)(16 * PADK) * 2;
            ldsm4(bh0, khi + bo0);
            ldsm4(bh1, khi + bo1);
            ldsm4(bl0, klo + bo0);
            ldsm4(bl1, klo + bo1);
#pragma unroll
            for (int nt = 0; nt < 4; nt++) {
                uint32_t ah[4], al[4];
                uint32_t ao = (uint32_t)((arow_k + kk * 16) * PADQ + nt * 16 + acq) * 2;
                ldsm4t(ah, qhi + ao);
                ldsm4t(al, qlo + ao);
                float* A0 = sacc[nt * 4 + 0];
                float* A1 = sacc[nt * 4 + 1];
                float* A2 = sacc[nt * 4 + 2];
                float* A3 = sacc[nt * 4 + 3];
                mma16816(A0, ah, bh0[0], bh0[1]);
                mma16816(A1, ah, bh0[2], bh0[3]);
                mma16816(A2, ah, bh1[0], bh1[1]);
                mma16816(A3, ah, bh1[2], bh1[3]);
                mma16816(A0, ah, bl0[0], bl0[1]);
                mma16816(A1, ah, bl0[2], bl0[3]);
                mma16816(A2, ah, bl1[0], bl1[1]);
                mma16816(A3, ah, bl1[2], bl1[3]);
                mma16816(A0, al, bh0[0], bh0[1]);
                mma16816(A1, al, bh0[2], bh0[3]);
                mma16816(A2, al, bh1[0], bh1[1]);
                mma16816(A3, al, bh1[2], bh1[3]);
            }
        }
        __syncthreads();
        if (hc < 15) conv_q(qv);
        if (hc < 14) ldg_q(hc + 2, qv);
    }

    issue_w(0, 0); CP_COMMIT();

    // ---------------- softmax over m (cross-warp m-reduction) ----------------
    float* pm = (float*)(smem + OFF_E);
    float* ps = (float*)(smem + OFF_E + 1024);
    float* rcp = (float*)(smem + OFF_RCP);

    float mx[4][2];
#pragma unroll
    for (int nt = 0; nt < 4; nt++) { mx[nt][0] = -3.4e38f; mx[nt][1] = -3.4e38f; }
#pragma unroll
    for (int t = 0; t < 16; t++) {
        int nt = t >> 2;
        mx[nt][0] = fmaxf(mx[nt][0], fmaxf(sacc[t][0], sacc[t][1]));
        mx[nt][1] = fmaxf(mx[nt][1], fmaxf(sacc[t][2], sacc[t][3]));
    }
#pragma unroll
    for (int nt = 0; nt < 4; nt++)
#pragma unroll
        for (int hf = 0; hf < 2; hf++) {
            mx[nt][hf] = fmaxf(mx[nt][hf], __shfl_xor_sync(0xFFFFFFFFu, mx[nt][hf], 1));
            mx[nt][hf] = fmaxf(mx[nt][hf], __shfl_xor_sync(0xFFFFFFFFu, mx[nt][hf], 2));
        }
    if (qq == 0) {
#pragma unroll
        for (int nt = 0; nt < 4; nt++)
#pragma unroll
            for (int hf = 0; hf < 2; hf++)
                pm[wid * 64 + nt * 16 + hf * 8 + rr] = mx[nt][hf];
    }
    __syncthreads();
    float rmax[4][2];
#pragma unroll
    for (int nt = 0; nt < 4; nt++)
#pragma unroll
        for (int hf = 0; hf < 2; hf++) {
            int n = nt * 16 + hf * 8 + rr;
            float v = fmaxf(pm[n], pm[64 + n]);
            v = fmaxf(v, fmaxf(pm[128 + n], pm[192 + n]));
            rmax[nt][hf] = v;
        }
    float sm[4][2];
#pragma unroll
    for (int nt = 0; nt < 4; nt++) { sm[nt][0] = 0.f; sm[nt][1] = 0.f; }
#pragma unroll
    for (int t = 0; t < 16; t++) {
        int nt = t >> 2;
        sacc[t][0] = __expf(sacc[t][0] - rmax[nt][0]);
        sacc[t][1] = __expf(sacc[t][1] - rmax[nt][0]);
        sacc[t][2] = __expf(sacc[t][2] - rmax[nt][1]);
        sacc[t][3] = __expf(sacc[t][3] - rmax[nt][1]);
        sm[nt][0] += sacc[t][0] + sacc[t][1];
        sm[nt][1] += sacc[t][2] + sacc[t][3];
    }
#pragma unroll
    for (int nt = 0; nt < 4; nt++)
#pragma unroll
        for (int hf = 0; hf < 2; hf++) {
            sm[nt][hf] += __shfl_xor_sync(0xFFFFFFFFu, sm[nt][hf], 1);
            sm[nt][hf] += __shfl_xor_sync(0xFFFFFFFFu, sm[nt][hf], 2);
        }
    if (qq == 0) {
#pragma unroll
        for (int nt = 0; nt < 4; nt++)
#pragma unroll
            for (int hf = 0; hf < 2; hf++)
                ps[wid * 64 + nt * 16 + hf * 8 + rr] = sm[nt][hf];
    }
    __syncthreads();
    if (wid == 0 && qq == 0) {
#pragma unroll
        for (int nt = 0; nt < 4; nt++)
#pragma unroll
            for (int hf = 0; hf < 2; hf++) {
                int n = nt * 16 + hf * 8 + rr;
                rcp[n] = 1.0f / (ps[n] + ps[64 + n] + ps[128 + n] + ps[192 + n]);
            }
    }
    __syncthreads();

    // ---- write unnormalized E (fp16) to smem [n64][m128] ----
#pragma unroll
    for (int t = 0; t < 16; t++) {
        int nt = t >> 2, u = t & 3;
        int m  = 32 * wid + (u >> 1) * 16 + (u & 1) * 8 + 2 * qq;
        int nr = nt * 16 + rr;
        *(uint32_t*)(smem + OFF_E + (size_t)nr * (PADE * 2) + m * 2) =
            packh2(sacc[t][0], sacc[t][1]);
        *(uint32_t*)(smem + OFF_E + (size_t)(nr + 8) * (PADE * 2) + m * 2) =
            packh2(sacc[t][2], sacc[t][3]);
    }
    __syncthreads();

    // ---- reload E as GEMM2 A-fragments (n-split) ----
    uint32_t ef[8][4];
#pragma unroll
    for (int kk = 0; kk < 8; kk++)
        ldsm4(ef[kk], sbase + OFF_E + e_off + kk * 32);
    const float r0 = ((float*)(smem + OFF_RCP))[16 * wid + rr];
    const float r1 = ((float*)(smem + OFF_RCP))[16 * wid + rr + 8];

    // -------- GEMM2 (n-split): C[n][h] = sum_m E[n][m] * Wp[h][m] --------
    float* outb = out + (size_t)b * HDIM * NDIM;
    float* stg = (float*)(smem + OFF_STG);

    for (int hc2 = 0; hc2 < 8; hc2++) {
        const int p = hc2 & 1;
        CP_WAIT(0);
        __syncthreads();
        if (hc2 < 7) { issue_w(hc2 + 1, p ^ 1); CP_COMMIT(); }

        float cacc[8][4];
#pragma unroll
        for (int t = 0; t < 8; t++)
#pragma unroll
            for (int j = 0; j < 4; j++) cacc[t][j] = 0.f;

        const uint32_t wb = sbase + OFF_WB + p * WB_SZ;
#pragma unroll
        for (int kk = 0; kk < 8; kk++) {
            uint32_t b0[4], b1[4], b2[4], b3[4];
            uint32_t ko = (uint32_t)(kk * 16) * 2;
            ldsm4(b0, wb + b_off_w + ko);
            ldsm4(b1, wb + b_off_w + (uint32_t)(16 * PADW) * 2 + ko);
            ldsm4(b2, wb + b_off_w + (uint32_t)(32 * PADW) * 2 + ko);
            ldsm4(b3, wb + b_off_w + (uint32_t)(48 * PADW) * 2 + ko);
            mma16816f(cacc[0], ef[kk], b0[0], b0[1]);
            mma16816f(cacc[1], ef[kk], b0[2], b0[3]);
            mma16816f(cacc[2], ef[kk], b1[0], b1[1]);
            mma16816f(cacc[3], ef[kk], b1[2], b1[3]);
            mma16816f(cacc[4], ef[kk], b2[0], b2[1]);
            mma16816f(cacc[5], ef[kk], b2[2], b2[3]);
            mma16816f(cacc[6], ef[kk], b3[0], b3[1]);
            mma16816f(cacc[7], ef[kk], b3[2], b3[3]);
        }

#pragma unroll
        for (int t = 0; t < 8; t++) {
            int hcl = t * 8 + 2 * qq;
            int n   = wid * 16 + rr;
            stg[(size_t)hcl * STGS + n]           = cacc[t][0] * r0;
            stg[(size_t)(hcl + 1) * STGS + n]     = cacc[t][1] * r0;
            stg[(size_t)hcl * STGS + n + 8]       = cacc[t][2] * r1;
            stg[(size_t)(hcl + 1) * STGS + n + 8] = cacc[t][3] * r1;
        }
        __syncthreads();

#pragma unroll
        for (int it = 0; it < 8; it++) {
            int f = it * 128 + tid, hr = f >> 4, n4 = (f & 15) << 2;
            float4 v = *(const float4*)(stg + (size_t)hr * STGS + n4);
            stcs4(outb + (size_t)(hc2 * 64 + hr) * NDIM + n0 + n4, v);
        }
    }
}

// ============================================================
extern "C" void kernel_launch(void* const* d_in, const int* in_sizes, int n_in,
                              void* d_out, int out_size) {
    const float* H      = (const float*)d_in[0];  // [32,512,64,64]
    const float* W      = (const float*)d_in[1];  // [32,256,128]
    const float* head_w = (const float*)d_in[2];  // [512,256]
    float* out = (float*)d_out;

    cudaFuncSetAttribute(proj_kernel,
                         cudaFuncAttributeMaxDynamicSharedMemorySize, PSMEM);
    cudaFuncSetAttribute(attn_kernel,
                         cudaFuncAttributeMaxDynamicSharedMemorySize, SMEM_DYN);

    proj_kernel<<<dim3(8, B_DIM), 256, PSMEM>>>(W, head_w);
    attn_kernel<<<dim3(NDIM / 64, B_DIM), 128, SMEM_DYN>>>(H, out);
}